// round 2
// baseline (speedup 1.0000x reference)
#include <cuda_runtime.h>
#include <math.h>

// ---------------- problem constants ----------------
constexpr int B_   = 64;
constexpr int C_   = 3;
constexpr int HW_  = 512;
constexpr int P_   = 16;
constexpr int D_   = 256;    // token dim
constexpr int G_   = 32;     // GH = GW
constexpr int NP_  = 1024;
constexpr int T_   = 1025;   // tokens (NP+1)
constexpr int HID_ = 1024;
constexpr int L_   = 6;
constexpr int NC_  = 1000;
constexpr int KH_  = 129;    // half-spectrum columns (0..128)
constexpr int KC_  = 768;    // C*P*P

// ---------------- scratch (device globals; no allocation) ----------------
__device__ float g_t   [B_*T_*D_];        // residual stream  (~67 MB)
__device__ float g_h   [B_*T_*D_];        // LN output        (~67 MB)
__device__ float g_hc  [B_*T_*KH_];       // h @ C2           (~34 MB)
__device__ float g_hs  [B_*T_*KH_];       // h @ S2           (~34 MB)
__device__ float g_mid [B_*T_*HID_];      // FFN hidden       (~269 MB)
__device__ float g_C1  [T_*T_];           // cos DFT 1025     (~4.2 MB)
__device__ float g_S1  [T_*T_];           // sin DFT 1025
__device__ float g_C2  [D_*KH_];          // cos DFT 256 (half)
__device__ float g_S2  [D_*KH_];
__device__ float g_wT  [KC_*D_];          // transposed conv weight
__device__ float g_pool[B_*D_];

// ---------------- init kernels ----------------
__global__ void k_initdft1() {
    int idx = blockIdx.x * blockDim.x + threadIdx.x;
    if (idx >= T_ * T_) return;
    int k = idx / T_, n = idx % T_;
    int prod = (int)(((long long)k * n) % T_);
    float ang = (float)(6.283185307179586 * (double)prod / (double)T_);
    float s, c; sincosf(ang, &s, &c);
    g_C1[idx] = c; g_S1[idx] = s;
}

__global__ void k_initdft2() {
    int idx = blockIdx.x * blockDim.x + threadIdx.x;
    if (idx >= D_ * KH_) return;
    int n2 = idx / KH_, k2 = idx % KH_;
    int prod = (n2 * k2) & (D_ - 1);
    float ang = (float)(6.283185307179586 * (double)prod / (double)D_);
    float s, c; sincosf(ang, &s, &c);
    g_C2[idx] = c; g_S2[idx] = s;
}

// transpose conv_w (D, C*P*P) -> (C*P*P, D) for coalesced GEMM B loads
__global__ void k_twt(const float* __restrict__ w) {
    int idx = blockIdx.x * blockDim.x + threadIdx.x;
    if (idx >= KC_ * D_) return;
    int k = idx >> 8, d = idx & 255;
    g_wT[idx] = w[d * KC_ + k];
}

// cls token row: t[b,0,:] = cls + pos[0,:]
__global__ void k_cls(const float* __restrict__ cls, const float* __restrict__ pos) {
    int idx = blockIdx.x * blockDim.x + threadIdx.x;   // 64*256
    int b = idx >> 8, d = idx & 255;
    g_t[(size_t)b * T_ * D_ + d] = cls[d] + pos[d];
}

// ---------------- patch-embed GEMM: 65536 x 256 x 768 ----------------
// t[b, 1+patch, d] = sum_k x_gather * wT[k,d] + conv_b[d] + pos[1+patch, d]
__global__ void k_patch(const float* __restrict__ x, const float* __restrict__ cb,
                        const float* __restrict__ pos) {
    __shared__ float As[16][65];
    __shared__ float Bs[16][65];
    int tid = threadIdx.x;
    int tx = tid & 15, ty = tid >> 4;
    int m0 = blockIdx.y * 64, n0 = blockIdx.x * 64;
    float acc[4][4] = {};
    for (int k0 = 0; k0 < KC_; k0 += 16) {
        #pragma unroll
        for (int l = 0; l < 4; l++) {
            int idx = tid + l * 256;
            int k = idx & 15, m = idx >> 4;
            int r = m0 + m, kg = k0 + k;
            int b = r >> 10, patch = r & 1023;
            int gh = patch >> 5, gw = patch & 31;
            int c = kg >> 8, p = (kg >> 4) & 15, q = kg & 15;
            As[k][m] = x[(((size_t)(b * 3 + c) * 512) + gh * 16 + p) * 512 + gw * 16 + q];
        }
        #pragma unroll
        for (int l = 0; l < 4; l++) {
            int idx = tid + l * 256;
            int n = idx & 63, k = idx >> 6;
            Bs[k][n] = g_wT[(k0 + k) * D_ + n0 + n];
        }
        __syncthreads();
        #pragma unroll
        for (int kk = 0; kk < 16; kk++) {
            float ra[4], rb[4];
            #pragma unroll
            for (int i = 0; i < 4; i++) ra[i] = As[kk][ty * 4 + i];
            #pragma unroll
            for (int j = 0; j < 4; j++) rb[j] = Bs[kk][tx * 4 + j];
            #pragma unroll
            for (int i = 0; i < 4; i++)
                #pragma unroll
                for (int j = 0; j < 4; j++) acc[i][j] += ra[i] * rb[j];
        }
        __syncthreads();
    }
    #pragma unroll
    for (int i = 0; i < 4; i++) {
        int r = m0 + ty * 4 + i;
        int b = r >> 10, patch = r & 1023;
        size_t base = ((size_t)b * T_ + 1 + patch) * D_;
        #pragma unroll
        for (int j = 0; j < 4; j++) {
            int d = n0 + tx * 4 + j;
            g_t[base + d] = acc[i][j] + cb[d] + pos[(1 + patch) * D_ + d];
        }
    }
}

// ---------------- LayerNorm rows of g_t -> g_h (warp per row) ----------------
__global__ void k_ln(const float* __restrict__ s, const float* __restrict__ bb) {
    int row  = blockIdx.x * 8 + (threadIdx.x >> 5);
    int lane = threadIdx.x & 31;
    const float* x = g_t + (size_t)row * D_;
    float v[8]; float sum = 0.f;
    #pragma unroll
    for (int i = 0; i < 8; i++) { v[i] = x[lane + i * 32]; sum += v[i]; }
    #pragma unroll
    for (int o = 16; o > 0; o >>= 1) sum += __shfl_xor_sync(0xffffffffu, sum, o);
    float mean = sum * (1.0f / 256.0f);
    float var = 0.f;
    #pragma unroll
    for (int i = 0; i < 8; i++) { float d = v[i] - mean; var += d * d; }
    #pragma unroll
    for (int o = 16; o > 0; o >>= 1) var += __shfl_xor_sync(0xffffffffu, var, o);
    float inv = rsqrtf(var * (1.0f / 256.0f) + 1e-5f);
    float* o2 = g_h + (size_t)row * D_;
    #pragma unroll
    for (int i = 0; i < 8; i++) {
        int c = lane + i * 32;
        o2[c] = (v[i] - mean) * inv * s[c] + bb[c];
    }
}

// ---------------- dim-axis DFT: Hc = h@C2, Hs = h@S2 (65600 x 129 x K256) ---
__global__ void k_dimdft() {
    __shared__ float As[16][65];
    __shared__ float Bc[16][65];
    __shared__ float Bz[16][65];
    int tid = threadIdx.x;
    int tx = tid & 15, ty = tid >> 4;
    int m0 = blockIdx.y * 64, n0 = blockIdx.x * 64;
    float ac[4][4] = {}, az[4][4] = {};
    for (int k0 = 0; k0 < D_; k0 += 16) {
        #pragma unroll
        for (int l = 0; l < 4; l++) {
            int idx = tid + l * 256;
            int k = idx & 15, m = idx >> 4;
            As[k][m] = g_h[(size_t)(m0 + m) * D_ + k0 + k];
        }
        #pragma unroll
        for (int l = 0; l < 4; l++) {
            int idx = tid + l * 256;
            int n = idx & 63, k = idx >> 6;
            int ng = n0 + n;
            float vc = 0.f, vz = 0.f;
            if (ng < KH_) {
                vc = g_C2[(k0 + k) * KH_ + ng];
                vz = g_S2[(k0 + k) * KH_ + ng];
            }
            Bc[k][n] = vc; Bz[k][n] = vz;
        }
        __syncthreads();
        #pragma unroll
        for (int kk = 0; kk < 16; kk++) {
            float ra[4], rc[4], rz[4];
            #pragma unroll
            for (int i = 0; i < 4; i++) ra[i] = As[kk][ty * 4 + i];
            #pragma unroll
            for (int j = 0; j < 4; j++) { rc[j] = Bc[kk][tx * 4 + j]; rz[j] = Bz[kk][tx * 4 + j]; }
            #pragma unroll
            for (int i = 0; i < 4; i++)
                #pragma unroll
                for (int j = 0; j < 4; j++) {
                    ac[i][j] += ra[i] * rc[j];
                    az[i][j] += ra[i] * rz[j];
                }
        }
        __syncthreads();
    }
    #pragma unroll
    for (int i = 0; i < 4; i++) {
        int r = m0 + ty * 4 + i;
        #pragma unroll
        for (int j = 0; j < 4; j++) {
            int n = n0 + tx * 4 + j;
            if (n < KH_) {
                g_hc[(size_t)r * KH_ + n] = ac[i][j];
                g_hs[(size_t)r * KH_ + n] = az[i][j];
            }
        }
    }
}

// ---------------- token-axis DFT + residual add ------------------------------
// U = C1 @ Hc, V = S1 @ Hs per batch; t[:,k2] += U-V; t[:,256-k2] += U+V
// C1/S1 are symmetric -> load A tiles row-wise (coalesced).
__global__ void k_tokendft() {
    __shared__ float Ac[16][65], Az[16][65], Bc[16][65], Bz[16][65];
    int tid = threadIdx.x;
    int tx = tid & 15, ty = tid >> 4;
    int m0 = blockIdx.y * 64;    // k1 tile
    int n0 = blockIdx.x * 64;    // k2 tile
    int b  = blockIdx.z;
    const float* hcb = g_hc + (size_t)b * T_ * KH_;
    const float* hsb = g_hs + (size_t)b * T_ * KH_;
    float U[4][4] = {}, V[4][4] = {};
    for (int k0 = 0; k0 < T_; k0 += 16) {
        #pragma unroll
        for (int l = 0; l < 4; l++) {
            int idx = tid + l * 256;
            int mm = idx & 63, kk = idx >> 6;
            int kg = k0 + kk, mg = m0 + mm;
            float vc = 0.f, vz = 0.f;
            if (kg < T_ && mg < T_) {
                size_t off = (size_t)kg * T_ + mg;   // symmetry: A[m][k] == A[k][m]
                vc = g_C1[off]; vz = g_S1[off];
            }
            Ac[kk][mm] = vc; Az[kk][mm] = vz;
        }
        #pragma unroll
        for (int l = 0; l < 4; l++) {
            int idx = tid + l * 256;
            int n = idx & 63, kk = idx >> 6;
            int kg = k0 + kk, ng = n0 + n;
            float vc = 0.f, vz = 0.f;
            if (kg < T_ && ng < KH_) {
                size_t off = (size_t)kg * KH_ + ng;
                vc = hcb[off]; vz = hsb[off];
            }
            Bc[kk][n] = vc; Bz[kk][n] = vz;
        }
        __syncthreads();
        #pragma unroll
        for (int kk = 0; kk < 16; kk++) {
            float rac[4], raz[4], rbc[4], rbz[4];
            #pragma unroll
            for (int i = 0; i < 4; i++) { rac[i] = Ac[kk][ty * 4 + i]; raz[i] = Az[kk][ty * 4 + i]; }
            #pragma unroll
            for (int j = 0; j < 4; j++) { rbc[j] = Bc[kk][tx * 4 + j]; rbz[j] = Bz[kk][tx * 4 + j]; }
            #pragma unroll
            for (int i = 0; i < 4; i++)
                #pragma unroll
                for (int j = 0; j < 4; j++) {
                    U[i][j] += rac[i] * rbc[j];
                    V[i][j] += raz[i] * rbz[j];
                }
        }
        __syncthreads();
    }
    float* tb = g_t + (size_t)b * T_ * D_;
    #pragma unroll
    for (int i = 0; i < 4; i++) {
        int k1 = m0 + ty * 4 + i;
        if (k1 >= T_) continue;
        #pragma unroll
        for (int j = 0; j < 4; j++) {
            int k2 = n0 + tx * 4 + j;
            if (k2 >= KH_) continue;
            float u = U[i][j], v = V[i][j];
            tb[(size_t)k1 * D_ + k2] += u - v;
            if (k2 >= 1 && k2 <= 127)
                tb[(size_t)k1 * D_ + (256 - k2)] += u + v;
        }
    }
}

// ---------------- FFN GEMM 1: mid = lrelu(h @ w1 + b1)  (65600x1024xK256) ----
__global__ void k_ffn1(const float* __restrict__ w, const float* __restrict__ bias) {
    __shared__ float As[16][65];
    __shared__ float Bs[16][65];
    int tid = threadIdx.x;
    int tx = tid & 15, ty = tid >> 4;
    int m0 = blockIdx.y * 64, n0 = blockIdx.x * 64;
    float acc[4][4] = {};
    for (int k0 = 0; k0 < D_; k0 += 16) {
        #pragma unroll
        for (int l = 0; l < 4; l++) {
            int idx = tid + l * 256;
            int k = idx & 15, m = idx >> 4;
            As[k][m] = g_h[(size_t)(m0 + m) * D_ + k0 + k];
        }
        #pragma unroll
        for (int l = 0; l < 4; l++) {
            int idx = tid + l * 256;
            int n = idx & 63, k = idx >> 6;
            Bs[k][n] = w[(size_t)(k0 + k) * HID_ + n0 + n];
        }
        __syncthreads();
        #pragma unroll
        for (int kk = 0; kk < 16; kk++) {
            float ra[4], rb[4];
            #pragma unroll
            for (int i = 0; i < 4; i++) ra[i] = As[kk][ty * 4 + i];
            #pragma unroll
            for (int j = 0; j < 4; j++) rb[j] = Bs[kk][tx * 4 + j];
            #pragma unroll
            for (int i = 0; i < 4; i++)
                #pragma unroll
                for (int j = 0; j < 4; j++) acc[i][j] += ra[i] * rb[j];
        }
        __syncthreads();
    }
    #pragma unroll
    for (int i = 0; i < 4; i++) {
        int r = m0 + ty * 4 + i;
        #pragma unroll
        for (int j = 0; j < 4; j++) {
            int n = n0 + tx * 4 + j;
            float z = acc[i][j] + bias[n];
            g_mid[(size_t)r * HID_ + n] = (z > 0.f) ? z : 0.01f * z;
        }
    }
}

// ---------------- FFN GEMM 2: t += mid @ w2 + b2  (65600x256xK1024) ----------
__global__ void k_ffn2(const float* __restrict__ w, const float* __restrict__ bias) {
    __shared__ float As[16][65];
    __shared__ float Bs[16][65];
    int tid = threadIdx.x;
    int tx = tid & 15, ty = tid >> 4;
    int m0 = blockIdx.y * 64, n0 = blockIdx.x * 64;
    float acc[4][4] = {};
    for (int k0 = 0; k0 < HID_; k0 += 16) {
        #pragma unroll
        for (int l = 0; l < 4; l++) {
            int idx = tid + l * 256;
            int k = idx & 15, m = idx >> 4;
            As[k][m] = g_mid[(size_t)(m0 + m) * HID_ + k0 + k];
        }
        #pragma unroll
        for (int l = 0; l < 4; l++) {
            int idx = tid + l * 256;
            int n = idx & 63, k = idx >> 6;
            Bs[k][n] = w[(size_t)(k0 + k) * D_ + n0 + n];
        }
        __syncthreads();
        #pragma unroll
        for (int kk = 0; kk < 16; kk++) {
            float ra[4], rb[4];
            #pragma unroll
            for (int i = 0; i < 4; i++) ra[i] = As[kk][ty * 4 + i];
            #pragma unroll
            for (int j = 0; j < 4; j++) rb[j] = Bs[kk][tx * 4 + j];
            #pragma unroll
            for (int i = 0; i < 4; i++)
                #pragma unroll
                for (int j = 0; j < 4; j++) acc[i][j] += ra[i] * rb[j];
        }
        __syncthreads();
    }
    #pragma unroll
    for (int i = 0; i < 4; i++) {
        int r = m0 + ty * 4 + i;
        #pragma unroll
        for (int j = 0; j < 4; j++) {
            int n = n0 + tx * 4 + j;
            g_t[(size_t)r * D_ + n] += acc[i][j] + bias[n];
        }
    }
}

// ---------------- mean pool over tokens ----------------
__global__ void k_pool() {
    int b = blockIdx.x, d = threadIdx.x;
    const float* p = g_t + (size_t)b * T_ * D_ + d;
    float s = 0.f;
    for (int tok = 0; tok < T_; tok++) s += p[(size_t)tok * D_];
    g_pool[b * D_ + d] = s * (1.0f / 1025.0f);
}

// ---------------- head: LN + linear + softmax (block per batch) --------------
__global__ void k_head(const float* __restrict__ s, const float* __restrict__ bb,
                       const float* __restrict__ W, const float* __restrict__ hb,
                       float* __restrict__ out) {
    __shared__ float sh[256];
    __shared__ float lnp[256];
    int b = blockIdx.x, tid = threadIdx.x;
    float x = g_pool[b * D_ + tid];
    sh[tid] = x; __syncthreads();
    for (int o = 128; o > 0; o >>= 1) { if (tid < o) sh[tid] += sh[tid + o]; __syncthreads(); }
    float mean = sh[0] * (1.0f / 256.0f);
    __syncthreads();
    float d = x - mean;
    sh[tid] = d * d; __syncthreads();
    for (int o = 128; o > 0; o >>= 1) { if (tid < o) sh[tid] += sh[tid + o]; __syncthreads(); }
    float inv = rsqrtf(sh[0] * (1.0f / 256.0f) + 1e-5f);
    __syncthreads();
    lnp[tid] = d * inv * s[tid] + bb[tid];
    __syncthreads();
    float lv[4];
    float lmax = -1e30f;
    #pragma unroll
    for (int j = 0; j < 4; j++) {
        int n = tid + j * 256;
        float acc = -1e30f;
        if (n < NC_) {
            acc = hb[n];
            for (int k = 0; k < 256; k++) acc += lnp[k] * W[k * NC_ + n];
            lmax = fmaxf(lmax, acc);
        }
        lv[j] = acc;
    }
    sh[tid] = lmax; __syncthreads();
    for (int o = 128; o > 0; o >>= 1) { if (tid < o) sh[tid] = fmaxf(sh[tid], sh[tid + o]); __syncthreads(); }
    float mx = sh[0]; __syncthreads();
    float esum = 0.f;
    #pragma unroll
    for (int j = 0; j < 4; j++) {
        int n = tid + j * 256;
        if (n < NC_) esum += expf(lv[j] - mx);
    }
    sh[tid] = esum; __syncthreads();
    for (int o = 128; o > 0; o >>= 1) { if (tid < o) sh[tid] += sh[tid + o]; __syncthreads(); }
    float tot = sh[0];
    #pragma unroll
    for (int j = 0; j < 4; j++) {
        int n = tid + j * 256;
        if (n < NC_) out[b * NC_ + n] = expf(lv[j] - mx) / tot;
    }
}

// ---------------- launch ----------------
extern "C" void kernel_launch(void* const* d_in, const int* in_sizes, int n_in,
                              void* d_out, int out_size) {
    const float* x      = (const float*)d_in[0];
    const float* conv_w = (const float*)d_in[1];
    const float* conv_b = (const float*)d_in[2];
    const float* pos    = (const float*)d_in[3];
    const float* cls    = (const float*)d_in[4];
    const float* ln1_s  = (const float*)d_in[5];
    const float* ln1_b  = (const float*)d_in[6];
    const float* ln2_s  = (const float*)d_in[7];
    const float* ln2_b  = (const float*)d_in[8];
    const float* w1     = (const float*)d_in[9];
    const float* b1     = (const float*)d_in[10];
    const float* w2     = (const float*)d_in[11];
    const float* b2     = (const float*)d_in[12];
    const float* hls    = (const float*)d_in[13];
    const float* hlb    = (const float*)d_in[14];
    const float* hw     = (const float*)d_in[15];
    const float* hb     = (const float*)d_in[16];
    float* out = (float*)d_out;

    k_initdft1<<<(T_ * T_ + 255) / 256, 256>>>();
    k_initdft2<<<(D_ * KH_ + 255) / 256, 256>>>();
    k_twt<<<(KC_ * D_ + 255) / 256, 256>>>(conv_w);
    k_patch<<<dim3(D_ / 64, (B_ * NP_) / 64), 256>>>(x, conv_b, pos);
    k_cls<<<(B_ * D_) / 256, 256>>>(cls, pos);

    for (int i = 0; i < L_; i++) {
        k_ln<<<(B_ * T_) / 8, 256>>>(ln1_s + i * D_, ln1_b + i * D_);
        k_dimdft<<<dim3((KH_ + 63) / 64, (B_ * T_) / 64), 256>>>();
        k_tokendft<<<dim3((KH_ + 63) / 64, (T_ + 63) / 64, B_), 256>>>();
        k_ln<<<(B_ * T_) / 8, 256>>>(ln2_s + i * D_, ln2_b + i * D_);
        k_ffn1<<<dim3(HID_ / 64, (B_ * T_) / 64), 256>>>(w1 + (size_t)i * D_ * HID_, b1 + i * HID_);
        k_ffn2<<<dim3(D_ / 64, (B_ * T_) / 64), 256>>>(w2 + (size_t)i * HID_ * D_, b2 + i * D_);
    }

    k_pool<<<B_, D_>>>();
    k_head<<<B_, 256>>>(hls, hlb, hw, hb, out);
}

// round 8
// speedup vs baseline: 1.6361x; 1.6361x over previous
#include <cuda_runtime.h>
#include <cuda_fp16.h>
#include <stdint.h>
#include <math.h>

// ---------------- problem constants ----------------
constexpr int B_   = 64;
constexpr int C_   = 3;
constexpr int HW_  = 512;
constexpr int P_   = 16;
constexpr int D_   = 256;    // token dim
constexpr int G_   = 32;     // GH = GW
constexpr int NP_  = 1024;
constexpr int T_   = 1025;   // tokens (NP+1)
constexpr int HID_ = 1024;
constexpr int L_   = 6;
constexpr int NC_  = 1000;
constexpr int KH_  = 129;    // half-spectrum columns (0..128)
constexpr int KC_  = 768;    // C*P*P
constexpr int M_   = B_ * T_; // 65600 rows

// ---------------- scratch (device globals; no allocation) ----------------
__device__ float  g_t   [B_*T_*D_];
__device__ float  g_h   [B_*T_*D_];
__device__ __half g_h16 [B_*T_*D_];
__device__ float  g_hc  [B_*T_*KH_];
__device__ float  g_hs  [B_*T_*KH_];
__device__ __half g_mid16[B_*T_*HID_];
__device__ float  g_C1  [T_*T_];
__device__ float  g_S1  [T_*T_];
__device__ float  g_C2  [D_*KH_];
__device__ float  g_S2  [D_*KH_];
__device__ float  g_wT  [KC_*D_];
__device__ float  g_pool[B_*D_];
__device__ __half g_w1h [L_*D_*HID_];
__device__ __half g_w2h [L_*HID_*D_];

// ---------------- mma helpers (note: operand lists spelled with a space
// after every opening brace so the source never contains brace-percent
// byte pairs that collide with the test-template renderer) ----------------
__device__ __forceinline__ void ldsm_x4(uint32_t* r, uint32_t addr) {
    asm volatile("ldmatrix.sync.aligned.m8n8.x4.shared.b16 { %0, %1, %2, %3 }, [ %4 ];"
                 : "=r"(r[0]), "=r"(r[1]), "=r"(r[2]), "=r"(r[3]) : "r"(addr));
}
__device__ __forceinline__ void ldsm_x4_t(uint32_t* r, uint32_t addr) {
    asm volatile("ldmatrix.sync.aligned.m8n8.x4.trans.shared.b16 { %0, %1, %2, %3 }, [ %4 ];"
                 : "=r"(r[0]), "=r"(r[1]), "=r"(r[2]), "=r"(r[3]) : "r"(addr));
}
__device__ __forceinline__ void mma16816(float* d, const uint32_t* a, const uint32_t* b) {
    asm volatile("mma.sync.aligned.m16n8k16.row.col.f32.f16.f16.f32 "
                 "{ %0, %1, %2, %3 }, { %4, %5, %6, %7 }, { %8, %9 }, { %0, %1, %2, %3 };"
                 : "+f"(d[0]), "+f"(d[1]), "+f"(d[2]), "+f"(d[3])
                 : "r"(a[0]), "r"(a[1]), "r"(a[2]), "r"(a[3]), "r"(b[0]), "r"(b[1]));
}

// ---------------- init kernels ----------------
__global__ void k_initdft1() {
    int idx = blockIdx.x * blockDim.x + threadIdx.x;
    if (idx >= T_ * T_) return;
    int k = idx / T_, n = idx % T_;
    int prod = (int)(((long long)k * n) % T_);
    float ang = (float)(6.283185307179586 * (double)prod / (double)T_);
    float s, c; sincosf(ang, &s, &c);
    g_C1[idx] = c; g_S1[idx] = s;
}

__global__ void k_initdft2() {
    int idx = blockIdx.x * blockDim.x + threadIdx.x;
    if (idx >= D_ * KH_) return;
    int n2 = idx / KH_, k2 = idx % KH_;
    int prod = (n2 * k2) & (D_ - 1);
    float ang = (float)(6.283185307179586 * (double)prod / (double)D_);
    float s, c; sincosf(ang, &s, &c);
    g_C2[idx] = c; g_S2[idx] = s;
}

__global__ void k_twt(const float* __restrict__ w) {
    int idx = blockIdx.x * blockDim.x + threadIdx.x;
    if (idx >= KC_ * D_) return;
    int k = idx >> 8, d = idx & 255;
    g_wT[idx] = w[d * KC_ + k];
}

__global__ void k_cvtw(const float* __restrict__ w1, const float* __restrict__ w2) {
    int i = blockIdx.x * blockDim.x + threadIdx.x;
    if (i >= L_ * D_ * HID_) return;
    g_w1h[i] = __float2half(w1[i]);
    g_w2h[i] = __float2half(w2[i]);
}

__global__ void k_cls(const float* __restrict__ cls, const float* __restrict__ pos) {
    int idx = blockIdx.x * blockDim.x + threadIdx.x;
    int b = idx >> 8, d = idx & 255;
    g_t[(size_t)b * T_ * D_ + d] = cls[d] + pos[d];
}

// ---------------- patch-embed GEMM (fp32) ----------------
__global__ void k_patch(const float* __restrict__ x, const float* __restrict__ cb,
                        const float* __restrict__ pos) {
    __shared__ float As[16][65];
    __shared__ float Bs[16][65];
    int tid = threadIdx.x;
    int tx = tid & 15, ty = tid >> 4;
    int m0 = blockIdx.y * 64, n0 = blockIdx.x * 64;
    float acc[4][4] = {};
    for (int k0 = 0; k0 < KC_; k0 += 16) {
        #pragma unroll
        for (int l = 0; l < 4; l++) {
            int idx = tid + l * 256;
            int k = idx & 15, m = idx >> 4;
            int r = m0 + m, kg = k0 + k;
            int b = r >> 10, patch = r & 1023;
            int gh = patch >> 5, gw = patch & 31;
            int c = kg >> 8, p = (kg >> 4) & 15, q = kg & 15;
            As[k][m] = x[(((size_t)(b * 3 + c) * 512) + gh * 16 + p) * 512 + gw * 16 + q];
        }
        #pragma unroll
        for (int l = 0; l < 4; l++) {
            int idx = tid + l * 256;
            int n = idx & 63, k = idx >> 6;
            Bs[k][n] = g_wT[(k0 + k) * D_ + n0 + n];
        }
        __syncthreads();
        #pragma unroll
        for (int kk = 0; kk < 16; kk++) {
            float ra[4], rb[4];
            #pragma unroll
            for (int i = 0; i < 4; i++) ra[i] = As[kk][ty * 4 + i];
            #pragma unroll
            for (int j = 0; j < 4; j++) rb[j] = Bs[kk][tx * 4 + j];
            #pragma unroll
            for (int i = 0; i < 4; i++)
                #pragma unroll
                for (int j = 0; j < 4; j++) acc[i][j] += ra[i] * rb[j];
        }
        __syncthreads();
    }
    #pragma unroll
    for (int i = 0; i < 4; i++) {
        int r = m0 + ty * 4 + i;
        int b = r >> 10, patch = r & 1023;
        size_t base = ((size_t)b * T_ + 1 + patch) * D_;
        #pragma unroll
        for (int j = 0; j < 4; j++) {
            int d = n0 + tx * 4 + j;
            g_t[base + d] = acc[i][j] + cb[d] + pos[(1 + patch) * D_ + d];
        }
    }
}

// ---------------- LayerNorm -> g_h (fp32) + g_h16 (fp16) ----------------
__global__ void k_ln(const float* __restrict__ s, const float* __restrict__ bb) {
    int row  = blockIdx.x * 8 + (threadIdx.x >> 5);
    int lane = threadIdx.x & 31;
    const float* x = g_t + (size_t)row * D_;
    float v[8]; float sum = 0.f;
    #pragma unroll
    for (int i = 0; i < 8; i++) { v[i] = x[lane + i * 32]; sum += v[i]; }
    #pragma unroll
    for (int o = 16; o > 0; o >>= 1) sum += __shfl_xor_sync(0xffffffffu, sum, o);
    float mean = sum * (1.0f / 256.0f);
    float var = 0.f;
    #pragma unroll
    for (int i = 0; i < 8; i++) { float d = v[i] - mean; var += d * d; }
    #pragma unroll
    for (int o = 16; o > 0; o >>= 1) var += __shfl_xor_sync(0xffffffffu, var, o);
    float inv = rsqrtf(var * (1.0f / 256.0f) + 1e-5f);
    float* o2 = g_h + (size_t)row * D_;
    __half* o3 = g_h16 + (size_t)row * D_;
    #pragma unroll
    for (int i = 0; i < 8; i++) {
        int c = lane + i * 32;
        float r = (v[i] - mean) * inv * s[c] + bb[c];
        o2[c] = r;
        o3[c] = __float2half(r);
    }
}

// ---------------- dim-axis DFT (fp32 SIMT) ----------------
__global__ void k_dimdft() {
    __shared__ float As[16][65];
    __shared__ float Bc[16][65];
    __shared__ float Bz[16][65];
    int tid = threadIdx.x;
    int tx = tid & 15, ty = tid >> 4;
    int m0 = blockIdx.y * 64, n0 = blockIdx.x * 64;
    float ac[4][4] = {}, az[4][4] = {};
    for (int k0 = 0; k0 < D_; k0 += 16) {
        #pragma unroll
        for (int l = 0; l < 4; l++) {
            int idx = tid + l * 256;
            int k = idx & 15, m = idx >> 4;
            As[k][m] = g_h[(size_t)(m0 + m) * D_ + k0 + k];
        }
        #pragma unroll
        for (int l = 0; l < 4; l++) {
            int idx = tid + l * 256;
            int n = idx & 63, k = idx >> 6;
            int ng = n0 + n;
            float vc = 0.f, vz = 0.f;
            if (ng < KH_) {
                vc = g_C2[(k0 + k) * KH_ + ng];
                vz = g_S2[(k0 + k) * KH_ + ng];
            }
            Bc[k][n] = vc; Bz[k][n] = vz;
        }
        __syncthreads();
        #pragma unroll
        for (int kk = 0; kk < 16; kk++) {
            float ra[4], rc[4], rz[4];
            #pragma unroll
            for (int i = 0; i < 4; i++) ra[i] = As[kk][ty * 4 + i];
            #pragma unroll
            for (int j = 0; j < 4; j++) { rc[j] = Bc[kk][tx * 4 + j]; rz[j] = Bz[kk][tx * 4 + j]; }
            #pragma unroll
            for (int i = 0; i < 4; i++)
                #pragma unroll
                for (int j = 0; j < 4; j++) {
                    ac[i][j] += ra[i] * rc[j];
                    az[i][j] += ra[i] * rz[j];
                }
        }
        __syncthreads();
    }
    #pragma unroll
    for (int i = 0; i < 4; i++) {
        int r = m0 + ty * 4 + i;
        #pragma unroll
        for (int j = 0; j < 4; j++) {
            int n = n0 + tx * 4 + j;
            if (n < KH_) {
                g_hc[(size_t)r * KH_ + n] = ac[i][j];
                g_hs[(size_t)r * KH_ + n] = az[i][j];
            }
        }
    }
}

// ---------------- token-axis DFT + residual add (fp32 SIMT) ------------------
__global__ void k_tokendft() {
    __shared__ float Ac[16][65], Az[16][65], Bc[16][65], Bz[16][65];
    int tid = threadIdx.x;
    int tx = tid & 15, ty = tid >> 4;
    int m0 = blockIdx.y * 64;
    int n0 = blockIdx.x * 64;
    int b  = blockIdx.z;
    const float* hcb = g_hc + (size_t)b * T_ * KH_;
    const float* hsb = g_hs + (size_t)b * T_ * KH_;
    float U[4][4] = {}, V[4][4] = {};
    for (int k0 = 0; k0 < T_; k0 += 16) {
        #pragma unroll
        for (int l = 0; l < 4; l++) {
            int idx = tid + l * 256;
            int mm = idx & 63, kk = idx >> 6;
            int kg = k0 + kk, mg = m0 + mm;
            float vc = 0.f, vz = 0.f;
            if (kg < T_ && mg < T_) {
                size_t off = (size_t)kg * T_ + mg;
                vc = g_C1[off]; vz = g_S1[off];
            }
            Ac[kk][mm] = vc; Az[kk][mm] = vz;
        }
        #pragma unroll
        for (int l = 0; l < 4; l++) {
            int idx = tid + l * 256;
            int n = idx & 63, kk = idx >> 6;
            int kg = k0 + kk, ng = n0 + n;
            float vc = 0.f, vz = 0.f;
            if (kg < T_ && ng < KH_) {
                size_t off = (size_t)kg * KH_ + ng;
                vc = hcb[off]; vz = hsb[off];
            }
            Bc[kk][n] = vc; Bz[kk][n] = vz;
        }
        __syncthreads();
        #pragma unroll
        for (int kk = 0; kk < 16; kk++) {
            float rac[4], raz[4], rbc[4], rbz[4];
            #pragma unroll
            for (int i = 0; i < 4; i++) { rac[i] = Ac[kk][ty * 4 + i]; raz[i] = Az[kk][ty * 4 + i]; }
            #pragma unroll
            for (int j = 0; j < 4; j++) { rbc[j] = Bc[kk][tx * 4 + j]; rbz[j] = Bz[kk][tx * 4 + j]; }
            #pragma unroll
            for (int i = 0; i < 4; i++)
                #pragma unroll
                for (int j = 0; j < 4; j++) {
                    U[i][j] += rac[i] * rbc[j];
                    V[i][j] += raz[i] * rbz[j];
                }
        }
        __syncthreads();
    }
    float* tb = g_t + (size_t)b * T_ * D_;
    #pragma unroll
    for (int i = 0; i < 4; i++) {
        int k1 = m0 + ty * 4 + i;
        if (k1 >= T_) continue;
        #pragma unroll
        for (int j = 0; j < 4; j++) {
            int k2 = n0 + tx * 4 + j;
            if (k2 >= KH_) continue;
            float u = U[i][j], v = V[i][j];
            tb[(size_t)k1 * D_ + k2] += u - v;
            if (k2 >= 1 && k2 <= 127)
                tb[(size_t)k1 * D_ + (256 - k2)] += u + v;
        }
    }
}

// ---------------- FFN via fp16 tensor cores ----------------------------------
// FFN1: mid16 = lrelu(h16 @ w1h[layer] + b1)   [M x 1024, K=256]
// FFN2: t   += mid16 @ w2h[layer] + b2         [M x 256,  K=1024]
// 256 threads = 8 warps (4 x 2), block tile 128x128, warp tile 32x64.
template<int N, int K, bool FFN1>
__global__ void k_ffn_mma(int layer, const float* __restrict__ bias) {
    __shared__ __half As[128][24];
    __shared__ __half Bs[16][136];
    int tid = threadIdx.x;
    int wid = tid >> 5, lane = tid & 31;
    int wm = wid & 3, wn = wid >> 2;
    int m0 = blockIdx.y * 128, n0 = blockIdx.x * 128;

    const __half* A  = FFN1 ? g_h16 : g_mid16;
    const __half* Bw = (FFN1 ? g_w1h : g_w2h) + (size_t)layer * D_ * HID_;

    float acc[2][8][4] = {};

    uint32_t a_addr[2], b_addr[4];
    #pragma unroll
    for (int mt = 0; mt < 2; mt++)
        a_addr[mt] = (uint32_t)__cvta_generic_to_shared(
            &As[wm * 32 + mt * 16 + (lane & 15)][(lane >> 4) * 8]);
    #pragma unroll
    for (int j = 0; j < 4; j++)
        b_addr[j] = (uint32_t)__cvta_generic_to_shared(
            &Bs[lane & 15][wn * 64 + j * 16 + (lane >> 4) * 8]);

    int arow = tid >> 1, acol = (tid & 1) * 8;
    int brow = tid >> 4, bcol = (tid & 15) * 8;
    int am = min(m0 + arow, M_ - 1);
    const __half* aptr = A + (size_t)am * K + acol;
    const __half* bptr = Bw + (size_t)brow * N + n0 + bcol;

    for (int k0 = 0; k0 < K; k0 += 16) {
        *(uint4*)&As[arow][acol] = *(const uint4*)(aptr + k0);
        *(uint4*)&Bs[brow][bcol] = *(const uint4*)(bptr + (size_t)k0 * N);
        __syncthreads();
        uint32_t af[2][4], bf[4][4];
        #pragma unroll
        for (int mt = 0; mt < 2; mt++) ldsm_x4(af[mt], a_addr[mt]);
        #pragma unroll
        for (int j = 0; j < 4; j++) ldsm_x4_t(bf[j], b_addr[j]);
        #pragma unroll
        for (int mt = 0; mt < 2; mt++)
            #pragma unroll
            for (int nt = 0; nt < 8; nt++)
                mma16816(acc[mt][nt], af[mt], &bf[nt >> 1][(nt & 1) * 2]);
        __syncthreads();
    }

    int r_base = m0 + wm * 32;
    int c_base = n0 + wn * 64;
    #pragma unroll
    for (int mt = 0; mt < 2; mt++) {
        #pragma unroll
        for (int nt = 0; nt < 8; nt++) {
            int row = r_base + mt * 16 + (lane >> 2);
            int col = c_base + nt * 8 + (lane & 3) * 2;
            float bz0 = bias[col], bz1 = bias[col + 1];
            #pragma unroll
            for (int h = 0; h < 2; h++) {
                int rr = row + h * 8;
                if (rr >= M_) continue;
                float v0 = acc[mt][nt][h * 2 + 0] + bz0;
                float v1 = acc[mt][nt][h * 2 + 1] + bz1;
                if (FFN1) {
                    v0 = (v0 > 0.f) ? v0 : 0.01f * v0;
                    v1 = (v1 > 0.f) ? v1 : 0.01f * v1;
                    *(__half2*)&g_mid16[(size_t)rr * N + col] = __floats2half2_rn(v0, v1);
                } else {
                    g_t[(size_t)rr * D_ + col]     += v0;
                    g_t[(size_t)rr * D_ + col + 1] += v1;
                }
            }
        }
    }
}

// ---------------- mean pool over tokens ----------------
__global__ void k_pool() {
    int b = blockIdx.x, d = threadIdx.x;
    const float* p = g_t + (size_t)b * T_ * D_ + d;
    float s = 0.f;
    for (int tok = 0; tok < T_; tok++) s += p[(size_t)tok * D_];
    g_pool[b * D_ + d] = s * (1.0f / 1025.0f);
}

// ---------------- head: LN + linear + softmax ----------------
__global__ void k_head(const float* __restrict__ s, const float* __restrict__ bb,
                       const float* __restrict__ W, const float* __restrict__ hb,
                       float* __restrict__ out) {
    __shared__ float sh[256];
    __shared__ float lnp[256];
    int b = blockIdx.x, tid = threadIdx.x;
    float x = g_pool[b * D_ + tid];
    sh[tid] = x; __syncthreads();
    for (int o = 128; o > 0; o >>= 1) { if (tid < o) sh[tid] += sh[tid + o]; __syncthreads(); }
    float mean = sh[0] * (1.0f / 256.0f);
    __syncthreads();
    float d = x - mean;
    sh[tid] = d * d; __syncthreads();
    for (int o = 128; o > 0; o >>= 1) { if (tid < o) sh[tid] += sh[tid + o]; __syncthreads(); }
    float inv = rsqrtf(sh[0] * (1.0f / 256.0f) + 1e-5f);
    __syncthreads();
    lnp[tid] = d * inv * s[tid] + bb[tid];
    __syncthreads();
    float lv[4];
    float lmax = -1e30f;
    #pragma unroll
    for (int j = 0; j < 4; j++) {
        int n = tid + j * 256;
        float acc = -1e30f;
        if (n < NC_) {
            acc = hb[n];
            for (int k = 0; k < 256; k++) acc += lnp[k] * W[k * NC_ + n];
            lmax = fmaxf(lmax, acc);
        }
        lv[j] = acc;
    }
    sh[tid] = lmax; __syncthreads();
    for (int o = 128; o > 0; o >>= 1) { if (tid < o) sh[tid] = fmaxf(sh[tid], sh[tid + o]); __syncthreads(); }
    float mx = sh[0]; __syncthreads();
    float esum = 0.f;
    #pragma unroll
    for (int j = 0; j < 4; j++) {
        int n = tid + j * 256;
        if (n < NC_) esum += expf(lv[j] - mx);
    }
    sh[tid] = esum; __syncthreads();
    for (int o = 128; o > 0; o >>= 1) { if (tid < o) sh[tid] += sh[tid + o]; __syncthreads(); }
    float tot = sh[0];
    #pragma unroll
    for (int j = 0; j < 4; j++) {
        int n = tid + j * 256;
        if (n < NC_) out[b * NC_ + n] = expf(lv[j] - mx) / tot;
    }
}

// ---------------- launch ----------------
extern "C" void kernel_launch(void* const* d_in, const int* in_sizes, int n_in,
                              void* d_out, int out_size) {
    const float* x      = (const float*)d_in[0];
    const float* conv_w = (const float*)d_in[1];
    const float* conv_b = (const float*)d_in[2];
    const float* pos    = (const float*)d_in[3];
    const float* cls    = (const float*)d_in[4];
    const float* ln1_s  = (const float*)d_in[5];
    const float* ln1_b  = (const float*)d_in[6];
    const float* ln2_s  = (const float*)d_in[7];
    const float* ln2_b  = (const float*)d_in[8];
    const float* w1     = (const float*)d_in[9];
    const float* b1     = (const float*)d_in[10];
    const float* w2     = (const float*)d_in[11];
    const float* b2     = (const float*)d_in[12];
    const float* hls    = (const float*)d_in[13];
    const float* hlb    = (const float*)d_in[14];
    const float* hw     = (const float*)d_in[15];
    const float* hb     = (const float*)d_in[16];
    float* out = (float*)d_out;

    k_initdft1<<<(T_ * T_ + 255) / 256, 256>>>();
    k_initdft2<<<(D_ * KH_ + 255) / 256, 256>>>();
    k_twt<<<(KC_ * D_ + 255) / 256, 256>>>(conv_w);
    k_cvtw<<<(L_ * D_ * HID_ + 255) / 256, 256>>>(w1, w2);
    k_patch<<<dim3(D_ / 64, (B_ * NP_) / 64), 256>>>(x, conv_b, pos);
    k_cls<<<(B_ * D_) / 256, 256>>>(cls, pos);

    const int MB = (M_ + 127) / 128;   // 513
    for (int i = 0; i < L_; i++) {
        k_ln<<<(B_ * T_) / 8, 256>>>(ln1_s + i * D_, ln1_b + i * D_);
        k_dimdft<<<dim3((KH_ + 63) / 64, (B_ * T_) / 64), 256>>>();
        k_tokendft<<<dim3((KH_ + 63) / 64, (T_ + 63) / 64, B_), 256>>>();
        k_ln<<<(B_ * T_) / 8, 256>>>(ln2_s + i * D_, ln2_b + i * D_);
        k_ffn_mma<HID_, D_, true ><<<dim3(HID_ / 128, MB), 256>>>(i, b1 + i * HID_);
        k_ffn_mma<D_, HID_, false><<<dim3(D_ / 128, MB), 256>>>(i, b2 + i * D_);
    }

    k_pool<<<B_, D_>>>();
    k_head<<<B_, 256>>>(hls, hlb, hw, hb, out);
}

// round 9
// speedup vs baseline: 2.7446x; 1.6776x over previous
#include <cuda_runtime.h>
#include <cuda_fp16.h>
#include <stdint.h>
#include <math.h>

// ---------------- problem constants ----------------
constexpr int B_   = 64;
constexpr int C_   = 3;
constexpr int HW_  = 512;
constexpr int P_   = 16;
constexpr int D_   = 256;    // token dim
constexpr int G_   = 32;     // GH = GW
constexpr int NP_  = 1024;
constexpr int T_   = 1025;   // tokens (NP+1)
constexpr int TH_  = 513;    // half-spectrum rows (0..512)
constexpr int HID_ = 1024;
constexpr int L_   = 6;
constexpr int NC_  = 1000;
constexpr int KH_  = 129;    // half-spectrum columns (0..128)
constexpr int KC_  = 768;    // C*P*P
constexpr int M_   = B_ * T_; // 65600 rows

// ---------------- scratch (device globals; no allocation) ----------------
__device__ float  g_t   [B_*T_*D_];
__device__ float  g_h   [B_*T_*D_];
__device__ __half g_h16 [B_*T_*D_];
__device__ float  g_hc  [B_*T_*KH_];
__device__ float  g_hs  [B_*T_*KH_];
__device__ __half g_mid16[B_*T_*HID_];
__device__ float  g_C1  [T_*T_];
__device__ float  g_S1  [T_*T_];
__device__ float  g_C2  [D_*KH_];
__device__ float  g_S2  [D_*KH_];
__device__ float  g_wT  [KC_*D_];
__device__ float  g_pool[B_*D_];
__device__ __half g_w1h [L_*D_*HID_];
__device__ __half g_w2h [L_*HID_*D_];

// ---------------- mma helpers (operand lists spelled with a space after
// every opening brace: the test-template renderer treats brace-percent as a
// directive, which broke rounds 3-6) ----------------
__device__ __forceinline__ void ldsm_x4(uint32_t* r, uint32_t addr) {
    asm volatile("ldmatrix.sync.aligned.m8n8.x4.shared.b16 { %0, %1, %2, %3 }, [ %4 ];"
                 : "=r"(r[0]), "=r"(r[1]), "=r"(r[2]), "=r"(r[3]) : "r"(addr));
}
__device__ __forceinline__ void ldsm_x4_t(uint32_t* r, uint32_t addr) {
    asm volatile("ldmatrix.sync.aligned.m8n8.x4.trans.shared.b16 { %0, %1, %2, %3 }, [ %4 ];"
                 : "=r"(r[0]), "=r"(r[1]), "=r"(r[2]), "=r"(r[3]) : "r"(addr));
}
__device__ __forceinline__ void mma16816(float* d, const uint32_t* a, const uint32_t* b) {
    asm volatile("mma.sync.aligned.m16n8k16.row.col.f32.f16.f16.f32 "
                 "{ %0, %1, %2, %3 }, { %4, %5, %6, %7 }, { %8, %9 }, { %0, %1, %2, %3 };"
                 : "+f"(d[0]), "+f"(d[1]), "+f"(d[2]), "+f"(d[3])
                 : "r"(a[0]), "r"(a[1]), "r"(a[2]), "r"(a[3]), "r"(b[0]), "r"(b[1]));
}

// ---------------- init kernels ----------------
__global__ void k_initdft1() {
    int idx = blockIdx.x * blockDim.x + threadIdx.x;
    if (idx >= T_ * T_) return;
    int k = idx / T_, n = idx % T_;
    int prod = (int)(((long long)k * n) % T_);
    float ang = (float)(6.283185307179586 * (double)prod / (double)T_);
    float s, c; sincosf(ang, &s, &c);
    g_C1[idx] = c; g_S1[idx] = s;
}

__global__ void k_initdft2() {
    int idx = blockIdx.x * blockDim.x + threadIdx.x;
    if (idx >= D_ * KH_) return;
    int n2 = idx / KH_, k2 = idx % KH_;
    int prod = (n2 * k2) & (D_ - 1);
    float ang = (float)(6.283185307179586 * (double)prod / (double)D_);
    float s, c; sincosf(ang, &s, &c);
    g_C2[idx] = c; g_S2[idx] = s;
}

__global__ void k_twt(const float* __restrict__ w) {
    int idx = blockIdx.x * blockDim.x + threadIdx.x;
    if (idx >= KC_ * D_) return;
    int k = idx >> 8, d = idx & 255;
    g_wT[idx] = w[d * KC_ + k];
}

__global__ void k_cvtw(const float* __restrict__ w1, const float* __restrict__ w2) {
    int i = blockIdx.x * blockDim.x + threadIdx.x;
    if (i >= L_ * D_ * HID_) return;
    g_w1h[i] = __float2half(w1[i]);
    g_w2h[i] = __float2half(w2[i]);
}

__global__ void k_cls(const float* __restrict__ cls, const float* __restrict__ pos) {
    int idx = blockIdx.x * blockDim.x + threadIdx.x;
    int b = idx >> 8, d = idx & 255;
    g_t[(size_t)b * T_ * D_ + d] = cls[d] + pos[d];
}

// ---------------- patch-embed GEMM (fp32) ----------------
__global__ void k_patch(const float* __restrict__ x, const float* __restrict__ cb,
                        const float* __restrict__ pos) {
    __shared__ float As[16][65];
    __shared__ float Bs[16][65];
    int tid = threadIdx.x;
    int tx = tid & 15, ty = tid >> 4;
    int m0 = blockIdx.y * 64, n0 = blockIdx.x * 64;
    float acc[4][4] = {};
    for (int k0 = 0; k0 < KC_; k0 += 16) {
        #pragma unroll
        for (int l = 0; l < 4; l++) {
            int idx = tid + l * 256;
            int k = idx & 15, m = idx >> 4;
            int r = m0 + m, kg = k0 + k;
            int b = r >> 10, patch = r & 1023;
            int gh = patch >> 5, gw = patch & 31;
            int c = kg >> 8, p = (kg >> 4) & 15, q = kg & 15;
            As[k][m] = x[(((size_t)(b * 3 + c) * 512) + gh * 16 + p) * 512 + gw * 16 + q];
        }
        #pragma unroll
        for (int l = 0; l < 4; l++) {
            int idx = tid + l * 256;
            int n = idx & 63, k = idx >> 6;
            Bs[k][n] = g_wT[(k0 + k) * D_ + n0 + n];
        }
        __syncthreads();
        #pragma unroll
        for (int kk = 0; kk < 16; kk++) {
            float ra[4], rb[4];
            #pragma unroll
            for (int i = 0; i < 4; i++) ra[i] = As[kk][ty * 4 + i];
            #pragma unroll
            for (int j = 0; j < 4; j++) rb[j] = Bs[kk][tx * 4 + j];
            #pragma unroll
            for (int i = 0; i < 4; i++)
                #pragma unroll
                for (int j = 0; j < 4; j++) acc[i][j] += ra[i] * rb[j];
        }
        __syncthreads();
    }
    #pragma unroll
    for (int i = 0; i < 4; i++) {
        int r = m0 + ty * 4 + i;
        int b = r >> 10, patch = r & 1023;
        size_t base = ((size_t)b * T_ + 1 + patch) * D_;
        #pragma unroll
        for (int j = 0; j < 4; j++) {
            int d = n0 + tx * 4 + j;
            g_t[base + d] = acc[i][j] + cb[d] + pos[(1 + patch) * D_ + d];
        }
    }
}

// ---------------- LayerNorm -> g_h (fp32) + g_h16 (fp16) ----------------
__global__ void k_ln(const float* __restrict__ s, const float* __restrict__ bb) {
    int row  = blockIdx.x * 8 + (threadIdx.x >> 5);
    int lane = threadIdx.x & 31;
    const float* x = g_t + (size_t)row * D_;
    float v[8]; float sum = 0.f;
    #pragma unroll
    for (int i = 0; i < 8; i++) { v[i] = x[lane + i * 32]; sum += v[i]; }
    #pragma unroll
    for (int o = 16; o > 0; o >>= 1) sum += __shfl_xor_sync(0xffffffffu, sum, o);
    float mean = sum * (1.0f / 256.0f);
    float var = 0.f;
    #pragma unroll
    for (int i = 0; i < 8; i++) { float d = v[i] - mean; var += d * d; }
    #pragma unroll
    for (int o = 16; o > 0; o >>= 1) var += __shfl_xor_sync(0xffffffffu, var, o);
    float inv = rsqrtf(var * (1.0f / 256.0f) + 1e-5f);
    float* o2 = g_h + (size_t)row * D_;
    __half* o3 = g_h16 + (size_t)row * D_;
    #pragma unroll
    for (int i = 0; i < 8; i++) {
        int c = lane + i * 32;
        float r = (v[i] - mean) * inv * s[c] + bb[c];
        o2[c] = r;
        o3[c] = __float2half(r);
    }
}

// ---------------- dim-axis DFT (fp32 SIMT) ----------------
__global__ void k_dimdft() {
    __shared__ float As[16][65];
    __shared__ float Bc[16][65];
    __shared__ float Bz[16][65];
    int tid = threadIdx.x;
    int tx = tid & 15, ty = tid >> 4;
    int m0 = blockIdx.y * 64, n0 = blockIdx.x * 64;
    float ac[4][4] = {}, az[4][4] = {};
    for (int k0 = 0; k0 < D_; k0 += 16) {
        #pragma unroll
        for (int l = 0; l < 4; l++) {
            int idx = tid + l * 256;
            int k = idx & 15, m = idx >> 4;
            As[k][m] = g_h[(size_t)(m0 + m) * D_ + k0 + k];
        }
        #pragma unroll
        for (int l = 0; l < 4; l++) {
            int idx = tid + l * 256;
            int n = idx & 63, k = idx >> 6;
            int ng = n0 + n;
            float vc = 0.f, vz = 0.f;
            if (ng < KH_) {
                vc = g_C2[(k0 + k) * KH_ + ng];
                vz = g_S2[(k0 + k) * KH_ + ng];
            }
            Bc[k][n] = vc; Bz[k][n] = vz;
        }
        __syncthreads();
        #pragma unroll
        for (int kk = 0; kk < 16; kk++) {
            float ra[4], rc[4], rz[4];
            #pragma unroll
            for (int i = 0; i < 4; i++) ra[i] = As[kk][ty * 4 + i];
            #pragma unroll
            for (int j = 0; j < 4; j++) { rc[j] = Bc[kk][tx * 4 + j]; rz[j] = Bz[kk][tx * 4 + j]; }
            #pragma unroll
            for (int i = 0; i < 4; i++)
                #pragma unroll
                for (int j = 0; j < 4; j++) {
                    ac[i][j] += ra[i] * rc[j];
                    az[i][j] += ra[i] * rz[j];
                }
        }
        __syncthreads();
    }
    #pragma unroll
    for (int i = 0; i < 4; i++) {
        int r = m0 + ty * 4 + i;
        #pragma unroll
        for (int j = 0; j < 4; j++) {
            int n = n0 + tx * 4 + j;
            if (n < KH_) {
                g_hc[(size_t)r * KH_ + n] = ac[i][j];
                g_hs[(size_t)r * KH_ + n] = az[i][j];
            }
        }
    }
}

// ---------------- token-axis DFT + residual add (fp32 SIMT) ------------------
// Row symmetry: C1[T-k1] = C1[k1], S1[T-k1] = -S1[k1], so computing
// U,V only for k1 in [0, 512] yields 4 outputs per (k1, k2):
//   y[k1     , k2]       = U - V        y[k1     , 256-k2] = U + V
//   y[1025-k1, k2]       = U + V        y[1025-k1, 256-k2] = U - V
__global__ void k_tokendft() {
    __shared__ float Ac[16][68], Az[16][68], Bc[16][68], Bz[16][68];
    int tid = threadIdx.x;
    int tx = tid & 15, ty = tid >> 4;
    int m0 = blockIdx.y * 64;    // k1 tile base (0..512)
    int n0 = blockIdx.x * 64;    // k2 tile base
    int b  = blockIdx.z;
    const float* hcb = g_hc + (size_t)b * T_ * KH_;
    const float* hsb = g_hs + (size_t)b * T_ * KH_;
    float U[4][4] = {}, V[4][4] = {};
    for (int k0 = 0; k0 < T_; k0 += 16) {
        #pragma unroll
        for (int l = 0; l < 4; l++) {
            int idx = tid + l * 256;
            int mm = idx & 63, kk = idx >> 6;
            int kg = k0 + kk, mg = m0 + mm;
            float vc = 0.f, vz = 0.f;
            if (kg < T_ && mg < T_) {
                size_t off = (size_t)kg * T_ + mg;   // C1/S1 symmetric
                vc = g_C1[off]; vz = g_S1[off];
            }
            Ac[kk][mm] = vc; Az[kk][mm] = vz;
        }
        #pragma unroll
        for (int l = 0; l < 4; l++) {
            int idx = tid + l * 256;
            int n = idx & 63, kk = idx >> 6;
            int kg = k0 + kk, ng = n0 + n;
            float vc = 0.f, vz = 0.f;
            if (kg < T_ && ng < KH_) {
                size_t off = (size_t)kg * KH_ + ng;
                vc = hcb[off]; vz = hsb[off];
            }
            Bc[kk][n] = vc; Bz[kk][n] = vz;
        }
        __syncthreads();
        #pragma unroll
        for (int kk = 0; kk < 16; kk++) {
            float4 a4c = *(const float4*)&Ac[kk][ty * 4];
            float4 a4z = *(const float4*)&Az[kk][ty * 4];
            float4 b4c = *(const float4*)&Bc[kk][tx * 4];
            float4 b4z = *(const float4*)&Bz[kk][tx * 4];
            float rac[4] = { a4c.x, a4c.y, a4c.z, a4c.w };
            float raz[4] = { a4z.x, a4z.y, a4z.z, a4z.w };
            float rbc[4] = { b4c.x, b4c.y, b4c.z, b4c.w };
            float rbz[4] = { b4z.x, b4z.y, b4z.z, b4z.w };
            #pragma unroll
            for (int i = 0; i < 4; i++)
                #pragma unroll
                for (int j = 0; j < 4; j++) {
                    U[i][j] += rac[i] * rbc[j];
                    V[i][j] += raz[i] * rbz[j];
                }
        }
        __syncthreads();
    }
    float* tb = g_t + (size_t)b * T_ * D_;
    #pragma unroll
    for (int i = 0; i < 4; i++) {
        int k1 = m0 + ty * 4 + i;
        if (k1 >= TH_) continue;
        #pragma unroll
        for (int j = 0; j < 4; j++) {
            int k2 = n0 + tx * 4 + j;
            if (k2 >= KH_) continue;
            float u = U[i][j], v = V[i][j];
            float upv = u + v, umv = u - v;
            tb[(size_t)k1 * D_ + k2] += umv;
            if (k2 >= 1 && k2 <= 127)
                tb[(size_t)k1 * D_ + (256 - k2)] += upv;
            if (k1 >= 1) {
                int r2 = T_ - k1;   // 513..1024
                tb[(size_t)r2 * D_ + k2] += upv;
                if (k2 >= 1 && k2 <= 127)
                    tb[(size_t)r2 * D_ + (256 - k2)] += umv;
            }
        }
    }
}

// ---------------- FFN via fp16 tensor cores ----------------------------------
// FFN1: mid16 = lrelu(h16 @ w1h[layer] + b1)   [M x 1024, K=256]
// FFN2: t   += mid16 @ w2h[layer] + b2         [M x 256,  K=1024]
// 256 threads = 8 warps (4 x 2), block tile 128x128, warp tile 32x64.
// K-slab of 32 per barrier pair (two 16-wide mma sub-steps).
template<int N, int K, bool FFN1>
__global__ void k_ffn_mma(int layer, const float* __restrict__ bias) {
    __shared__ __half As[128][40];    // 32 k + 8 pad (80B row stride)
    __shared__ __half Bs[32][136];    // 128 n + 8 pad (272B row stride)
    int tid = threadIdx.x;
    int wid = tid >> 5, lane = tid & 31;
    int wm = wid & 3, wn = wid >> 2;
    int m0 = blockIdx.y * 128, n0 = blockIdx.x * 128;

    const __half* A  = FFN1 ? g_h16 : g_mid16;
    const __half* Bw = (FFN1 ? g_w1h : g_w2h) + (size_t)layer * D_ * HID_;

    float acc[2][8][4] = {};

    uint32_t a_addr[2], b_addr[4];
    #pragma unroll
    for (int mt = 0; mt < 2; mt++)
        a_addr[mt] = (uint32_t)__cvta_generic_to_shared(
            &As[wm * 32 + mt * 16 + (lane & 15)][(lane >> 4) * 8]);
    #pragma unroll
    for (int j = 0; j < 4; j++)
        b_addr[j] = (uint32_t)__cvta_generic_to_shared(
            &Bs[lane & 15][wn * 64 + j * 16 + (lane >> 4) * 8]);

    for (int k0 = 0; k0 < K; k0 += 32) {
        #pragma unroll
        for (int l = 0; l < 2; l++) {
            int v = tid + l * 256;
            int ar = v >> 2, ac = (v & 3) * 8;
            int am = min(m0 + ar, M_ - 1);
            *(uint4*)&As[ar][ac] = *(const uint4*)(A + (size_t)am * K + k0 + ac);
        }
        #pragma unroll
        for (int l = 0; l < 2; l++) {
            int v = tid + l * 256;
            int br = v >> 4, bc = (v & 15) * 8;
            *(uint4*)&Bs[br][bc] = *(const uint4*)(Bw + (size_t)(k0 + br) * N + n0 + bc);
        }
        __syncthreads();
        #pragma unroll
        for (int ksub = 0; ksub < 2; ksub++) {
            uint32_t af[2][4], bf[4][4];
            #pragma unroll
            for (int mt = 0; mt < 2; mt++) ldsm_x4(af[mt], a_addr[mt] + ksub * 32);
            #pragma unroll
            for (int j = 0; j < 4; j++) ldsm_x4_t(bf[j], b_addr[j] + ksub * 4352);
            #pragma unroll
            for (int mt = 0; mt < 2; mt++)
                #pragma unroll
                for (int nt = 0; nt < 8; nt++)
                    mma16816(acc[mt][nt], af[mt], &bf[nt >> 1][(nt & 1) * 2]);
        }
        __syncthreads();
    }

    int r_base = m0 + wm * 32;
    int c_base = n0 + wn * 64;
    #pragma unroll
    for (int mt = 0; mt < 2; mt++) {
        #pragma unroll
        for (int nt = 0; nt < 8; nt++) {
            int row = r_base + mt * 16 + (lane >> 2);
            int col = c_base + nt * 8 + (lane & 3) * 2;
            float bz0 = bias[col], bz1 = bias[col + 1];
            #pragma unroll
            for (int h = 0; h < 2; h++) {
                int rr = row + h * 8;
                if (rr >= M_) continue;
                float v0 = acc[mt][nt][h * 2 + 0] + bz0;
                float v1 = acc[mt][nt][h * 2 + 1] + bz1;
                if (FFN1) {
                    v0 = (v0 > 0.f) ? v0 : 0.01f * v0;
                    v1 = (v1 > 0.f) ? v1 : 0.01f * v1;
                    *(__half2*)&g_mid16[(size_t)rr * N + col] = __floats2half2_rn(v0, v1);
                } else {
                    g_t[(size_t)rr * D_ + col]     += v0;
                    g_t[(size_t)rr * D_ + col + 1] += v1;
                }
            }
        }
    }
}

// ---------------- mean pool over tokens ----------------
__global__ void k_pool() {
    int b = blockIdx.x, d = threadIdx.x;
    const float* p = g_t + (size_t)b * T_ * D_ + d;
    float s = 0.f;
    for (int tok = 0; tok < T_; tok++) s += p[(size_t)tok * D_];
    g_pool[b * D_ + d] = s * (1.0f / 1025.0f);
}

// ---------------- head: LN + linear + softmax ----------------
__global__ void k_head(const float* __restrict__ s, const float* __restrict__ bb,
                       const float* __restrict__ W, const float* __restrict__ hb,
                       float* __restrict__ out) {
    __shared__ float sh[256];
    __shared__ float lnp[256];
    int b = blockIdx.x, tid = threadIdx.x;
    float x = g_pool[b * D_ + tid];
    sh[tid] = x; __syncthreads();
    for (int o = 128; o > 0; o >>= 1) { if (tid < o) sh[tid] += sh[tid + o]; __syncthreads(); }
    float mean = sh[0] * (1.0f / 256.0f);
    __syncthreads();
    float d = x - mean;
    sh[tid] = d * d; __syncthreads();
    for (int o = 128; o > 0; o >>= 1) { if (tid < o) sh[tid] += sh[tid + o]; __syncthreads(); }
    float inv = rsqrtf(sh[0] * (1.0f / 256.0f) + 1e-5f);
    __syncthreads();
    lnp[tid] = d * inv * s[tid] + bb[tid];
    __syncthreads();
    float lv[4];
    float lmax = -1e30f;
    #pragma unroll
    for (int j = 0; j < 4; j++) {
        int n = tid + j * 256;
        float acc = -1e30f;
        if (n < NC_) {
            acc = hb[n];
            for (int k = 0; k < 256; k++) acc += lnp[k] * W[k * NC_ + n];
            lmax = fmaxf(lmax, acc);
        }
        lv[j] = acc;
    }
    sh[tid] = lmax; __syncthreads();
    for (int o = 128; o > 0; o >>= 1) { if (tid < o) sh[tid] = fmaxf(sh[tid], sh[tid + o]); __syncthreads(); }
    float mx = sh[0]; __syncthreads();
    float esum = 0.f;
    #pragma unroll
    for (int j = 0; j < 4; j++) {
        int n = tid + j * 256;
        if (n < NC_) esum += expf(lv[j] - mx);
    }
    sh[tid] = esum; __syncthreads();
    for (int o = 128; o > 0; o >>= 1) { if (tid < o) sh[tid] += sh[tid + o]; __syncthreads(); }
    float tot = sh[0];
    #pragma unroll
    for (int j = 0; j < 4; j++) {
        int n = tid + j * 256;
        if (n < NC_) out[b * NC_ + n] = expf(lv[j] - mx) / tot;
    }
}

// ---------------- launch ----------------
extern "C" void kernel_launch(void* const* d_in, const int* in_sizes, int n_in,
                              void* d_out, int out_size) {
    const float* x      = (const float*)d_in[0];
    const float* conv_w = (const float*)d_in[1];
    const float* conv_b = (const float*)d_in[2];
    const float* pos    = (const float*)d_in[3];
    const float* cls    = (const float*)d_in[4];
    const float* ln1_s  = (const float*)d_in[5];
    const float* ln1_b  = (const float*)d_in[6];
    const float* ln2_s  = (const float*)d_in[7];
    const float* ln2_b  = (const float*)d_in[8];
    const float* w1     = (const float*)d_in[9];
    const float* b1     = (const float*)d_in[10];
    const float* w2     = (const float*)d_in[11];
    const float* b2     = (const float*)d_in[12];
    const float* hls    = (const float*)d_in[13];
    const float* hlb    = (const float*)d_in[14];
    const float* hw     = (const float*)d_in[15];
    const float* hb     = (const float*)d_in[16];
    float* out = (float*)d_out;

    k_initdft1<<<(T_ * T_ + 255) / 256, 256>>>();
    k_initdft2<<<(D_ * KH_ + 255) / 256, 256>>>();
    k_twt<<<(KC_ * D_ + 255) / 256, 256>>>(conv_w);
    k_cvtw<<<(L_ * D_ * HID_ + 255) / 256, 256>>>(w1, w2);
    k_patch<<<dim3(D_ / 64, (B_ * NP_) / 64), 256>>>(x, conv_b, pos);
    k_cls<<<(B_ * D_) / 256, 256>>>(cls, pos);

    const int MB = (M_ + 127) / 128;   // 513
    for (int i = 0; i < L_; i++) {
        k_ln<<<(B_ * T_) / 8, 256>>>(ln1_s + i * D_, ln1_b + i * D_);
        k_dimdft<<<dim3((KH_ + 63) / 64, (B_ * T_) / 64), 256>>>();
        k_tokendft<<<dim3((KH_ + 63) / 64, (TH_ + 63) / 64, B_), 256>>>();
        k_ln<<<(B_ * T_) / 8, 256>>>(ln2_s + i * D_, ln2_b + i * D_);
        k_ffn_mma<HID_, D_, true ><<<dim3(HID_ / 128, MB), 256>>>(i, b1 + i * HID_);
        k_ffn_mma<D_, HID_, false><<<dim3(D_ / 128, MB), 256>>>(i, b2 + i * D_);
    }

    k_pool<<<B_, D_>>>();
    k_head<<<B_, 256>>>(hls, hlb, hw, hb, out);
}

// round 10
// speedup vs baseline: 4.5468x; 1.6566x over previous
#include <cuda_runtime.h>
#include <cuda_fp16.h>
#include <stdint.h>
#include <math.h>

// ---------------- problem constants ----------------
constexpr int B_   = 64;
constexpr int C_   = 3;
constexpr int HW_  = 512;
constexpr int P_   = 16;
constexpr int D_   = 256;    // token dim
constexpr int G_   = 32;     // GH = GW
constexpr int NP_  = 1024;
constexpr int T_   = 1025;   // tokens (NP+1)
constexpr int TH_  = 513;    // half-spectrum rows (0..512)
constexpr int TP_  = 1056;   // tokens padded to 32-multiple for mma K loop
constexpr int HID_ = 1024;
constexpr int L_   = 6;
constexpr int NC_  = 1000;
constexpr int KH_  = 129;    // half-spectrum columns (0..128)
constexpr int KN_  = 128;    // mma-handled spectrum columns (0..127)
constexpr int KC_  = 768;    // C*P*P
constexpr int M_   = B_ * T_; // 65600 rows

// ---------------- scratch (device globals; no allocation) ----------------
__device__ float  g_t   [B_*T_*D_];        // residual stream
__device__ __half g_hh  [B_*T_*D_];        // LN output, fp16 hi
__device__ __half g_hl  [B_*T_*D_];        // LN output, fp16 lo
__device__ float  g_hc128[B_*TP_];         // dim-DFT Nyquist col (alternating sums)
__device__ __half g_hch [B_*TP_*KN_];      // Hc hi (pad token rows zero)
__device__ __half g_hcl [B_*TP_*KN_];      // Hc lo
__device__ __half g_hsh [B_*TP_*KN_];      // Hs hi
__device__ __half g_hsl [B_*TP_*KN_];      // Hs lo
__device__ float  g_U   [B_*TH_*KN_];      // token-DFT cosine part
__device__ __half g_mid16[B_*T_*HID_];
__device__ float  g_C1f [TH_*T_];          // fp32 C1 rows 0..512 (Nyquist MV)
__device__ __half g_C1h [TH_*TP_];         // split token-DFT matrices (pad cols zero)
__device__ __half g_C1l [TH_*TP_];
__device__ __half g_S1h [TH_*TP_];
__device__ __half g_S1l [TH_*TP_];
__device__ __half g_C2h [D_*KN_];          // split dim-DFT matrices
__device__ __half g_C2l [D_*KN_];
__device__ __half g_S2h [D_*KN_];
__device__ __half g_S2l [D_*KN_];
__device__ float  g_wT  [KC_*D_];
__device__ float  g_pool[B_*D_];
__device__ __half g_w1h [L_*D_*HID_];
__device__ __half g_w2h [L_*HID_*D_];

// ---------------- mma helpers (spaces after braces: template-renderer safe) --
__device__ __forceinline__ void ldsm_x4(uint32_t* r, uint32_t addr) {
    asm volatile("ldmatrix.sync.aligned.m8n8.x4.shared.b16 { %0, %1, %2, %3 }, [ %4 ];"
                 : "=r"(r[0]), "=r"(r[1]), "=r"(r[2]), "=r"(r[3]) : "r"(addr));
}
__device__ __forceinline__ void ldsm_x4_t(uint32_t* r, uint32_t addr) {
    asm volatile("ldmatrix.sync.aligned.m8n8.x4.trans.shared.b16 { %0, %1, %2, %3 }, [ %4 ];"
                 : "=r"(r[0]), "=r"(r[1]), "=r"(r[2]), "=r"(r[3]) : "r"(addr));
}
__device__ __forceinline__ void mma16816(float* d, const uint32_t* a, const uint32_t* b) {
    asm volatile("mma.sync.aligned.m16n8k16.row.col.f32.f16.f16.f32 "
                 "{ %0, %1, %2, %3 }, { %4, %5, %6, %7 }, { %8, %9 }, { %0, %1, %2, %3 };"
                 : "+f"(d[0]), "+f"(d[1]), "+f"(d[2]), "+f"(d[3])
                 : "r"(a[0]), "r"(a[1]), "r"(a[2]), "r"(a[3]), "r"(b[0]), "r"(b[1]));
}
__device__ __forceinline__ void split16(float x, __half& h, __half& l) {
    h = __float2half(x);
    l = __float2half(x - __half2float(h));
}

// ---------------- init kernels ----------------
__global__ void k_init1f() {       // fp32 C1, rows 0..512
    int idx = blockIdx.x * blockDim.x + threadIdx.x;
    if (idx >= TH_ * T_) return;
    int k = idx / T_, n = idx % T_;
    int prod = (int)(((long long)k * n) % T_);
    g_C1f[idx] = cosf((float)(6.283185307179586 * (double)prod / (double)T_));
}

__global__ void k_init1s() {       // split fp16 C1/S1, rows 0..512, cols padded
    int idx = blockIdx.x * blockDim.x + threadIdx.x;
    if (idx >= TH_ * TP_) return;
    int k = idx / TP_, n = idx % TP_;
    float c = 0.f, s = 0.f;
    if (n < T_) {
        int prod = (int)(((long long)k * n) % T_);
        float ang = (float)(6.283185307179586 * (double)prod / (double)T_);
        sincosf(ang, &s, &c);
    }
    __half h, l;
    split16(c, h, l); g_C1h[idx] = h; g_C1l[idx] = l;
    split16(s, h, l); g_S1h[idx] = h; g_S1l[idx] = l;
}

__global__ void k_init2s() {       // split fp16 C2/S2, cols 0..127
    int idx = blockIdx.x * blockDim.x + threadIdx.x;
    if (idx >= D_ * KN_) return;
    int n2 = idx / KN_, k2 = idx % KN_;
    int prod = (n2 * k2) & (D_ - 1);
    float ang = (float)(6.283185307179586 * (double)prod / (double)D_);
    float s, c; sincosf(ang, &s, &c);
    __half h, l;
    split16(c, h, l); g_C2h[idx] = h; g_C2l[idx] = l;
    split16(s, h, l); g_S2h[idx] = h; g_S2l[idx] = l;
}

__global__ void k_twt(const float* __restrict__ w) {
    int idx = blockIdx.x * blockDim.x + threadIdx.x;
    if (idx >= KC_ * D_) return;
    int k = idx >> 8, d = idx & 255;
    g_wT[idx] = w[d * KC_ + k];
}

__global__ void k_cvtw(const float* __restrict__ w1, const float* __restrict__ w2) {
    int i = blockIdx.x * blockDim.x + threadIdx.x;
    if (i >= L_ * D_ * HID_) return;
    g_w1h[i] = __float2half(w1[i]);
    g_w2h[i] = __float2half(w2[i]);
}

__global__ void k_cls(const float* __restrict__ cls, const float* __restrict__ pos) {
    int idx = blockIdx.x * blockDim.x + threadIdx.x;
    int b = idx >> 8, d = idx & 255;
    g_t[(size_t)b * T_ * D_ + d] = cls[d] + pos[d];
}

// ---------------- patch-embed GEMM (fp32) ----------------
__global__ void k_patch(const float* __restrict__ x, const float* __restrict__ cb,
                        const float* __restrict__ pos) {
    __shared__ float As[16][65];
    __shared__ float Bs[16][65];
    int tid = threadIdx.x;
    int tx = tid & 15, ty = tid >> 4;
    int m0 = blockIdx.y * 64, n0 = blockIdx.x * 64;
    float acc[4][4] = {};
    for (int k0 = 0; k0 < KC_; k0 += 16) {
        #pragma unroll
        for (int l = 0; l < 4; l++) {
            int idx = tid + l * 256;
            int k = idx & 15, m = idx >> 4;
            int r = m0 + m, kg = k0 + k;
            int b = r >> 10, patch = r & 1023;
            int gh = patch >> 5, gw = patch & 31;
            int c = kg >> 8, p = (kg >> 4) & 15, q = kg & 15;
            As[k][m] = x[(((size_t)(b * 3 + c) * 512) + gh * 16 + p) * 512 + gw * 16 + q];
        }
        #pragma unroll
        for (int l = 0; l < 4; l++) {
            int idx = tid + l * 256;
            int n = idx & 63, k = idx >> 6;
            Bs[k][n] = g_wT[(k0 + k) * D_ + n0 + n];
        }
        __syncthreads();
        #pragma unroll
        for (int kk = 0; kk < 16; kk++) {
            float ra[4], rb[4];
            #pragma unroll
            for (int i = 0; i < 4; i++) ra[i] = As[kk][ty * 4 + i];
            #pragma unroll
            for (int j = 0; j < 4; j++) rb[j] = Bs[kk][tx * 4 + j];
            #pragma unroll
            for (int i = 0; i < 4; i++)
                #pragma unroll
                for (int j = 0; j < 4; j++) acc[i][j] += ra[i] * rb[j];
        }
        __syncthreads();
    }
    #pragma unroll
    for (int i = 0; i < 4; i++) {
        int r = m0 + ty * 4 + i;
        int b = r >> 10, patch = r & 1023;
        size_t base = ((size_t)b * T_ + 1 + patch) * D_;
        #pragma unroll
        for (int j = 0; j < 4; j++) {
            int d = n0 + tx * 4 + j;
            g_t[base + d] = acc[i][j] + cb[d] + pos[(1 + patch) * D_ + d];
        }
    }
}

// ---------------- LayerNorm -> split fp16 (hi, lo) + Nyquist alt-sum --------
__global__ void k_ln(const float* __restrict__ s, const float* __restrict__ bb) {
    int row  = blockIdx.x * 8 + (threadIdx.x >> 5);
    int lane = threadIdx.x & 31;
    const float* x = g_t + (size_t)row * D_;
    float v[8]; float sum = 0.f;
    #pragma unroll
    for (int i = 0; i < 8; i++) { v[i] = x[lane + i * 32]; sum += v[i]; }
    #pragma unroll
    for (int o = 16; o > 0; o >>= 1) sum += __shfl_xor_sync(0xffffffffu, sum, o);
    float mean = sum * (1.0f / 256.0f);
    float var = 0.f;
    #pragma unroll
    for (int i = 0; i < 8; i++) { float d = v[i] - mean; var += d * d; }
    #pragma unroll
    for (int o = 16; o > 0; o >>= 1) var += __shfl_xor_sync(0xffffffffu, var, o);
    float inv = rsqrtf(var * (1.0f / 256.0f) + 1e-5f);
    __half* oh = g_hh + (size_t)row * D_;
    __half* ol = g_hl + (size_t)row * D_;
    float asum = 0.f;
    #pragma unroll
    for (int i = 0; i < 8; i++) {
        int c = lane + i * 32;
        float r = (v[i] - mean) * inv * s[c] + bb[c];
        __half h, l; split16(r, h, l);
        oh[c] = h; ol[c] = l;
        asum += r;
    }
    // alternating-sign row sum = Hc[:,128]  (C2 col 128 = (-1)^n, S2 col 128 = 0)
    float part = (lane & 1) ? -asum : asum;
    #pragma unroll
    for (int o = 16; o > 0; o >>= 1) part += __shfl_xor_sync(0xffffffffu, part, o);
    if (lane == 0) {
        int b = row / 1025, tok = row - b * 1025;
        g_hc128[b * TP_ + tok] = part;
    }
}

// ---------------- split-fp16 mma GEMM for both DFT stages --------------------
// MODE 0: Hc = h @ C2      (M=65600, K=256)  -> split store g_hch/g_hcl
// MODE 1: Hs = h @ S2      (M=65600, K=256)  -> split store g_hsh/g_hsl
// MODE 2: U  = C1 @ Hc[b]  (M=513,   K=1056) -> g_U
// MODE 3: V  = S1 @ Hs[b]  (M=513,   K=1056) -> fused U+-V residual writes
// C = Ah*Bh + Ah*Bl + Al*Bh (exact products, fp32 accumulate; Al*Bl ~ 2^-22)
template<int MODE>
__global__ void k_dftmma() {
    constexpr bool DIMS = (MODE < 2);
    constexpr int KTOT = DIMS ? 256 : TP_;
    constexpr int NSLAB = KTOT / 32;
    const int MROWS = DIMS ? M_ : TH_;

    __shared__ __half Ash[128][40];
    __shared__ __half Asl[128][40];
    __shared__ __half Bsh[32][136];
    __shared__ __half Bsl[32][136];

    int tid = threadIdx.x;
    int wid = tid >> 5, lane = tid & 31;
    int wm = wid & 3, wn = wid >> 2;
    int m0 = blockIdx.y * 128;
    int b = blockIdx.z;

    const __half *Ah, *Al, *Bh, *Bl;
    if (MODE == 0)      { Ah = g_hh;  Al = g_hl;  Bh = g_C2h; Bl = g_C2l; }
    else if (MODE == 1) { Ah = g_hh;  Al = g_hl;  Bh = g_S2h; Bl = g_S2l; }
    else if (MODE == 2) { Ah = g_C1h; Al = g_C1l;
                          Bh = g_hch + (size_t)b * TP_ * KN_;
                          Bl = g_hcl + (size_t)b * TP_ * KN_; }
    else                { Ah = g_S1h; Al = g_S1l;
                          Bh = g_hsh + (size_t)b * TP_ * KN_;
                          Bl = g_hsl + (size_t)b * TP_ * KN_; }

    float acc[2][8][4] = {};

    uint32_t ah_addr[2], al_addr[2], bh_addr[4], bl_addr[4];
    #pragma unroll
    for (int mt = 0; mt < 2; mt++) {
        ah_addr[mt] = (uint32_t)__cvta_generic_to_shared(
            &Ash[wm * 32 + mt * 16 + (lane & 15)][(lane >> 4) * 8]);
        al_addr[mt] = (uint32_t)__cvta_generic_to_shared(
            &Asl[wm * 32 + mt * 16 + (lane & 15)][(lane >> 4) * 8]);
    }
    #pragma unroll
    for (int j = 0; j < 4; j++) {
        bh_addr[j] = (uint32_t)__cvta_generic_to_shared(
            &Bsh[lane & 15][wn * 64 + j * 16 + (lane >> 4) * 8]);
        bl_addr[j] = (uint32_t)__cvta_generic_to_shared(
            &Bsl[lane & 15][wn * 64 + j * 16 + (lane >> 4) * 8]);
    }

    for (int ks = 0; ks < NSLAB; ks++) {
        int k0 = ks * 32;
        #pragma unroll
        for (int l = 0; l < 2; l++) {
            int v = tid + l * 256;
            int ar = v >> 2, ac = (v & 3) * 8;
            int am = min(m0 + ar, MROWS - 1);
            *(uint4*)&Ash[ar][ac] = *(const uint4*)(Ah + (size_t)am * KTOT + k0 + ac);
            *(uint4*)&Asl[ar][ac] = *(const uint4*)(Al + (size_t)am * KTOT + k0 + ac);
        }
        #pragma unroll
        for (int l = 0; l < 2; l++) {
            int v = tid + l * 256;
            int br = v >> 4, bc = (v & 15) * 8;
            *(uint4*)&Bsh[br][bc] = *(const uint4*)(Bh + (size_t)(k0 + br) * KN_ + bc);
            *(uint4*)&Bsl[br][bc] = *(const uint4*)(Bl + (size_t)(k0 + br) * KN_ + bc);
        }
        __syncthreads();
        #pragma unroll
        for (int ksub = 0; ksub < 2; ksub++) {
            uint32_t afh[2][4], afl[2][4], bfh[4][4], bfl[4][4];
            #pragma unroll
            for (int mt = 0; mt < 2; mt++) {
                ldsm_x4(afh[mt], ah_addr[mt] + ksub * 32);
                ldsm_x4(afl[mt], al_addr[mt] + ksub * 32);
            }
            #pragma unroll
            for (int j = 0; j < 4; j++) {
                ldsm_x4_t(bfh[j], bh_addr[j] + ksub * 4352);
                ldsm_x4_t(bfl[j], bl_addr[j] + ksub * 4352);
            }
            #pragma unroll
            for (int mt = 0; mt < 2; mt++)
                #pragma unroll
                for (int nt = 0; nt < 8; nt++) {
                    mma16816(acc[mt][nt], afh[mt], &bfh[nt >> 1][(nt & 1) * 2]);
                    mma16816(acc[mt][nt], afh[mt], &bfl[nt >> 1][(nt & 1) * 2]);
                    mma16816(acc[mt][nt], afl[mt], &bfh[nt >> 1][(nt & 1) * 2]);
                }
        }
        __syncthreads();
    }

    #pragma unroll
    for (int mt = 0; mt < 2; mt++) {
        #pragma unroll
        for (int nt = 0; nt < 8; nt++) {
            int row = m0 + wm * 32 + mt * 16 + (lane >> 2);
            int col = wn * 64 + nt * 8 + (lane & 3) * 2;
            #pragma unroll
            for (int h2 = 0; h2 < 2; h2++) {
                int rr = row + h2 * 8;
                if (DIMS) {
                    if (rr >= M_) continue;
                    int bb = rr / 1025, tok = rr - bb * 1025;
                    size_t off = ((size_t)bb * TP_ + tok) * KN_ + col;
                    #pragma unroll
                    for (int q = 0; q < 2; q++) {
                        __half h, l; split16(acc[mt][nt][h2 * 2 + q], h, l);
                        if (MODE == 0) { g_hch[off + q] = h; g_hcl[off + q] = l; }
                        else           { g_hsh[off + q] = h; g_hsl[off + q] = l; }
                    }
                } else if (MODE == 2) {
                    if (rr >= TH_) continue;
                    size_t off = ((size_t)b * TH_ + rr) * KN_ + col;
                    g_U[off]     = acc[mt][nt][h2 * 2 + 0];
                    g_U[off + 1] = acc[mt][nt][h2 * 2 + 1];
                } else {
                    if (rr >= TH_) continue;
                    const float* urow = g_U + ((size_t)b * TH_ + rr) * KN_;
                    float* tb = g_t + (size_t)b * T_ * D_;
                    #pragma unroll
                    for (int q = 0; q < 2; q++) {
                        int k2 = col + q;
                        float vv = acc[mt][nt][h2 * 2 + q];
                        float u = urow[k2];
                        float upv = u + vv, umv = u - vv;
                        tb[(size_t)rr * D_ + k2] += umv;
                        if (k2 >= 1) tb[(size_t)rr * D_ + (256 - k2)] += upv;
                        if (rr >= 1) {
                            size_t r2 = (size_t)(T_ - rr);
                            tb[r2 * D_ + k2] += upv;
                            if (k2 >= 1) tb[r2 * D_ + (256 - k2)] += umv;
                        }
                    }
                }
            }
        }
    }
}

// ---------------- token-DFT Nyquist column (k2 = 128): V = 0 ----------------
__global__ void k_tok128() {
    int warp = threadIdx.x >> 5, lane = threadIdx.x & 31;
    int k1 = blockIdx.x * 8 + warp;
    int b  = blockIdx.y;
    if (k1 >= TH_) return;
    const float* cr = g_C1f + (size_t)k1 * T_;
    const float* hv = g_hc128 + (size_t)b * TP_;
    float s = 0.f;
    for (int n = lane; n < T_; n += 32) s += cr[n] * hv[n];
    #pragma unroll
    for (int o = 16; o > 0; o >>= 1) s += __shfl_xor_sync(0xffffffffu, s, o);
    if (lane == 0) {
        float* tb = g_t + (size_t)b * T_ * D_;
        tb[(size_t)k1 * D_ + 128] += s;
        if (k1 >= 1) tb[(size_t)(T_ - k1) * D_ + 128] += s;
    }
}

// ---------------- FFN via fp16 tensor cores ----------------------------------
template<int N, int K, bool FFN1>
__global__ void k_ffn_mma(int layer, const float* __restrict__ bias) {
    __shared__ __half As[128][40];
    __shared__ __half Bs[32][136];
    int tid = threadIdx.x;
    int wid = tid >> 5, lane = tid & 31;
    int wm = wid & 3, wn = wid >> 2;
    int m0 = blockIdx.y * 128, n0 = blockIdx.x * 128;

    const __half* A  = FFN1 ? g_hh : g_mid16;
    const __half* Bw = (FFN1 ? g_w1h : g_w2h) + (size_t)layer * D_ * HID_;

    float acc[2][8][4] = {};

    uint32_t a_addr[2], b_addr[4];
    #pragma unroll
    for (int mt = 0; mt < 2; mt++)
        a_addr[mt] = (uint32_t)__cvta_generic_to_shared(
            &As[wm * 32 + mt * 16 + (lane & 15)][(lane >> 4) * 8]);
    #pragma unroll
    for (int j = 0; j < 4; j++)
        b_addr[j] = (uint32_t)__cvta_generic_to_shared(
            &Bs[lane & 15][wn * 64 + j * 16 + (lane >> 4) * 8]);

    for (int k0 = 0; k0 < K; k0 += 32) {
        #pragma unroll
        for (int l = 0; l < 2; l++) {
            int v = tid + l * 256;
            int ar = v >> 2, ac = (v & 3) * 8;
            int am = min(m0 + ar, M_ - 1);
            *(uint4*)&As[ar][ac] = *(const uint4*)(A + (size_t)am * K + k0 + ac);
        }
        #pragma unroll
        for (int l = 0; l < 2; l++) {
            int v = tid + l * 256;
            int br = v >> 4, bc = (v & 15) * 8;
            *(uint4*)&Bs[br][bc] = *(const uint4*)(Bw + (size_t)(k0 + br) * N + n0 + bc);
        }
        __syncthreads();
        #pragma unroll
        for (int ksub = 0; ksub < 2; ksub++) {
            uint32_t af[2][4], bf[4][4];
            #pragma unroll
            for (int mt = 0; mt < 2; mt++) ldsm_x4(af[mt], a_addr[mt] + ksub * 32);
            #pragma unroll
            for (int j = 0; j < 4; j++) ldsm_x4_t(bf[j], b_addr[j] + ksub * 4352);
            #pragma unroll
            for (int mt = 0; mt < 2; mt++)
                #pragma unroll
                for (int nt = 0; nt < 8; nt++)
                    mma16816(acc[mt][nt], af[mt], &bf[nt >> 1][(nt & 1) * 2]);
        }
        __syncthreads();
    }

    int r_base = m0 + wm * 32;
    int c_base = n0 + wn * 64;
    #pragma unroll
    for (int mt = 0; mt < 2; mt++) {
        #pragma unroll
        for (int nt = 0; nt < 8; nt++) {
            int row = r_base + mt * 16 + (lane >> 2);
            int col = c_base + nt * 8 + (lane & 3) * 2;
            float bz0 = bias[col], bz1 = bias[col + 1];
            #pragma unroll
            for (int h = 0; h < 2; h++) {
                int rr = row + h * 8;
                if (rr >= M_) continue;
                float v0 = acc[mt][nt][h * 2 + 0] + bz0;
                float v1 = acc[mt][nt][h * 2 + 1] + bz1;
                if (FFN1) {
                    v0 = (v0 > 0.f) ? v0 : 0.01f * v0;
                    v1 = (v1 > 0.f) ? v1 : 0.01f * v1;
                    *(__half2*)&g_mid16[(size_t)rr * N + col] = __floats2half2_rn(v0, v1);
                } else {
                    g_t[(size_t)rr * D_ + col]     += v0;
                    g_t[(size_t)rr * D_ + col + 1] += v1;
                }
            }
        }
    }
}

// ---------------- mean pool over tokens ----------------
__global__ void k_pool() {
    int b = blockIdx.x, d = threadIdx.x;
    const float* p = g_t + (size_t)b * T_ * D_ + d;
    float s = 0.f;
    for (int tok = 0; tok < T_; tok++) s += p[(size_t)tok * D_];
    g_pool[b * D_ + d] = s * (1.0f / 1025.0f);
}

// ---------------- head: LN + linear + softmax ----------------
__global__ void k_head(const float* __restrict__ s, const float* __restrict__ bb,
                       const float* __restrict__ W, const float* __restrict__ hb,
                       float* __restrict__ out) {
    __shared__ float sh[256];
    __shared__ float lnp[256];
    int b = blockIdx.x, tid = threadIdx.x;
    float x = g_pool[b * D_ + tid];
    sh[tid] = x; __syncthreads();
    for (int o = 128; o > 0; o >>= 1) { if (tid < o) sh[tid] += sh[tid + o]; __syncthreads(); }
    float mean = sh[0] * (1.0f / 256.0f);
    __syncthreads();
    float d = x - mean;
    sh[tid] = d * d; __syncthreads();
    for (int o = 128; o > 0; o >>= 1) { if (tid < o) sh[tid] += sh[tid + o]; __syncthreads(); }
    float inv = rsqrtf(sh[0] * (1.0f / 256.0f) + 1e-5f);
    __syncthreads();
    lnp[tid] = d * inv * s[tid] + bb[tid];
    __syncthreads();
    float lv[4];
    float lmax = -1e30f;
    #pragma unroll
    for (int j = 0; j < 4; j++) {
        int n = tid + j * 256;
        float acc = -1e30f;
        if (n < NC_) {
            acc = hb[n];
            for (int k = 0; k < 256; k++) acc += lnp[k] * W[k * NC_ + n];
            lmax = fmaxf(lmax, acc);
        }
        lv[j] = acc;
    }
    sh[tid] = lmax; __syncthreads();
    for (int o = 128; o > 0; o >>= 1) { if (tid < o) sh[tid] = fmaxf(sh[tid], sh[tid + o]); __syncthreads(); }
    float mx = sh[0]; __syncthreads();
    float esum = 0.f;
    #pragma unroll
    for (int j = 0; j < 4; j++) {
        int n = tid + j * 256;
        if (n < NC_) esum += expf(lv[j] - mx);
    }
    sh[tid] = esum; __syncthreads();
    for (int o = 128; o > 0; o >>= 1) { if (tid < o) sh[tid] += sh[tid + o]; __syncthreads(); }
    float tot = sh[0];
    #pragma unroll
    for (int j = 0; j < 4; j++) {
        int n = tid + j * 256;
        if (n < NC_) out[b * NC_ + n] = expf(lv[j] - mx) / tot;
    }
}

// ---------------- launch ----------------
extern "C" void kernel_launch(void* const* d_in, const int* in_sizes, int n_in,
                              void* d_out, int out_size) {
    const float* x      = (const float*)d_in[0];
    const float* conv_w = (const float*)d_in[1];
    const float* conv_b = (const float*)d_in[2];
    const float* pos    = (const float*)d_in[3];
    const float* cls    = (const float*)d_in[4];
    const float* ln1_s  = (const float*)d_in[5];
    const float* ln1_b  = (const float*)d_in[6];
    const float* ln2_s  = (const float*)d_in[7];
    const float* ln2_b  = (const float*)d_in[8];
    const float* w1     = (const float*)d_in[9];
    const float* b1     = (const float*)d_in[10];
    const float* w2     = (const float*)d_in[11];
    const float* b2     = (const float*)d_in[12];
    const float* hls    = (const float*)d_in[13];
    const float* hlb    = (const float*)d_in[14];
    const float* hw     = (const float*)d_in[15];
    const float* hb     = (const float*)d_in[16];
    float* out = (float*)d_out;

    k_init1f<<<(TH_ * T_ + 255) / 256, 256>>>();
    k_init1s<<<(TH_ * TP_ + 255) / 256, 256>>>();
    k_init2s<<<(D_ * KN_ + 255) / 256, 256>>>();
    k_twt<<<(KC_ * D_ + 255) / 256, 256>>>(conv_w);
    k_cvtw<<<(L_ * D_ * HID_ + 255) / 256, 256>>>(w1, w2);
    k_patch<<<dim3(D_ / 64, (B_ * NP_) / 64), 256>>>(x, conv_b, pos);
    k_cls<<<(B_ * D_) / 256, 256>>>(cls, pos);

    const int MB  = (M_ + 127) / 128;    // 513
    const int MBT = (TH_ + 127) / 128;   // 5
    for (int i = 0; i < L_; i++) {
        k_ln<<<(B_ * T_) / 8, 256>>>(ln1_s + i * D_, ln1_b + i * D_);
        k_dftmma<0><<<dim3(1, MB, 1), 256>>>();
        k_dftmma<1><<<dim3(1, MB, 1), 256>>>();
        k_dftmma<2><<<dim3(1, MBT, B_), 256>>>();
        k_dftmma<3><<<dim3(1, MBT, B_), 256>>>();
        k_tok128<<<dim3((TH_ + 7) / 8, B_), 256>>>();
        k_ln<<<(B_ * T_) / 8, 256>>>(ln2_s + i * D_, ln2_b + i * D_);
        k_ffn_mma<HID_, D_, true ><<<dim3(HID_ / 128, MB), 256>>>(i, b1 + i * HID_);
        k_ffn_mma<D_, HID_, false><<<dim3(D_ / 128, MB), 256>>>(i, b2 + i * D_);
    }

    k_pool<<<B_, D_>>>();
    k_head<<<B_, 256>>>(hls, hlb, hw, hb, out);
}